// round 4
// baseline (speedup 1.0000x reference)
#include <cuda_runtime.h>
#include <math.h>

#define L_SEQ 2048
#define NB 4
#define EM 512
#define NH 8
#define HD 64
#define RR (L_SEQ*NB)       // 8192 rows
#define EPS 1e-6f
#define ATTN_SCALE 0.125f   // 1/sqrt(64)

// Scratch (device globals — no allocation allowed)
__device__ float g_Q[(size_t)NB*NH*L_SEQ*HD];   // (n,h,l,d)
__device__ float g_K[(size_t)NB*NH*L_SEQ*HD];
__device__ float g_Vp[(size_t)NB*NH*L_SEQ*HD];  // max(v+shift,eps)^p
__device__ float g_O[(size_t)RR*EM];            // out_h in (L,N,E) layout

// ---------------------------------------------------------------------------
// Kernel 1: fused Q/K/V projection.  y = X @ W^T + b, scattered to (n,h,l,d).
// z = blockIdx.z selects q/k/v. For v, applies shift/clamp/pow (GeM pre-pool).
// 64x64 tile, BK=16, 256 threads, 4x4 per thread.
// ---------------------------------------------------------------------------
__global__ __launch_bounds__(256) void proj_kernel(
    const float* __restrict__ qin, const float* __restrict__ kin,
    const float* __restrict__ vin,
    const float* __restrict__ W, const float* __restrict__ bias,
    const float* __restrict__ pp, const float* __restrict__ shift)
{
    int z = blockIdx.z;
    const float* X  = (z == 0) ? qin : (z == 1) ? kin : vin;
    const float* Wz = W + (size_t)z * EM * EM;
    const float* bz = bias + z * EM;

    __shared__ float As[64][17];
    __shared__ float Bs[64][17];

    int tid = threadIdx.x;
    int tx = tid & 15, ty = tid >> 4;
    int rowBase = blockIdx.x * 64, colBase = blockIdx.y * 64;

    float acc[4][4] = {};

    for (int k0 = 0; k0 < EM; k0 += 16) {
        #pragma unroll
        for (int i = 0; i < 4; i++) {
            int idx = tid + i * 256;
            int m = idx >> 4, kk = idx & 15;
            As[m][kk] = X[(size_t)(rowBase + m) * EM + k0 + kk];
            Bs[m][kk] = Wz[(size_t)(colBase + m) * EM + k0 + kk];
        }
        __syncthreads();
        #pragma unroll
        for (int kk = 0; kk < 16; kk++) {
            float a[4], b[4];
            #pragma unroll
            for (int i = 0; i < 4; i++) { a[i] = As[ty*4+i][kk]; b[i] = Bs[tx*4+i][kk]; }
            #pragma unroll
            for (int i = 0; i < 4; i++)
                #pragma unroll
                for (int j = 0; j < 4; j++) acc[i][j] += a[i] * b[j];
        }
        __syncthreads();
    }

    #pragma unroll
    for (int i = 0; i < 4; i++) {
        int r = rowBase + ty * 4 + i;
        int l = r >> 2, n = r & 3;           // r = l*NB + n, NB=4
        #pragma unroll
        for (int j = 0; j < 4; j++) {
            int e = colBase + tx * 4 + j;
            float val = acc[i][j] + bz[e];
            int h = e >> 6, d = e & 63;
            size_t dst = ((size_t)(n * NH + h) * L_SEQ + l) * HD + d;
            if (z == 0)      g_Q[dst] = val;
            else if (z == 1) g_K[dst] = val;
            else             g_Vp[dst] = powf(fmaxf(val + shift[e], EPS), pp[e]);
        }
    }
}

// ---------------------------------------------------------------------------
// Kernel 2: flash attention over (n,h), 64-row Q tiles, streaming 64-row K/Vp
// tiles with online softmax.  Epilogue applies GeM inverse power.
// blockIdx.y = n*NH + h, blockIdx.x = q row tile.  256 threads, 4x4/thread.
// ---------------------------------------------------------------------------
__global__ __launch_bounds__(256) void attn_kernel(
    const float* __restrict__ pp, const float* __restrict__ shift)
{
    extern __shared__ float sm[];
    float* Qs = sm;                 // 64 x 65
    float* Ks = sm + 64 * 65;
    float* Vs = sm + 2 * 64 * 65;
    float* Ps = sm + 3 * 64 * 65;
    __shared__ float m_s[64], l_s[64], alpha_s[64];

    int nh = blockIdx.y;
    int rowBase = blockIdx.x * 64;
    const float* Qb = g_Q  + (size_t)nh * L_SEQ * HD;
    const float* Kb = g_K  + (size_t)nh * L_SEQ * HD;
    const float* Vb = g_Vp + (size_t)nh * L_SEQ * HD;

    int tid = threadIdx.x;
    int tx = tid & 15, ty = tid >> 4;

    // Load Q tile
    #pragma unroll
    for (int i = 0; i < 16; i++) {
        int idx = tid + i * 256;
        int m = idx >> 6, d = idx & 63;
        Qs[m * 65 + d] = Qb[(size_t)(rowBase + m) * HD + d];
    }
    if (tid < 64) { m_s[tid] = -INFINITY; l_s[tid] = 0.0f; }

    float acc[4][4] = {};
    __syncthreads();

    for (int j0 = 0; j0 < L_SEQ; j0 += 64) {
        // Load K, Vp tiles
        #pragma unroll
        for (int i = 0; i < 16; i++) {
            int idx = tid + i * 256;
            int m = idx >> 6, d = idx & 63;
            Ks[m * 65 + d] = Kb[(size_t)(j0 + m) * HD + d];
            Vs[m * 65 + d] = Vb[(size_t)(j0 + m) * HD + d];
        }
        __syncthreads();

        // S = Q K^T * scale  -> Ps
        {
            float s[4][4] = {};
            #pragma unroll
            for (int k = 0; k < 64; k++) {
                float a[4], b[4];
                #pragma unroll
                for (int i = 0; i < 4; i++) { a[i] = Qs[(ty*4+i)*65 + k]; b[i] = Ks[(tx*4+i)*65 + k]; }
                #pragma unroll
                for (int i = 0; i < 4; i++)
                    #pragma unroll
                    for (int jj = 0; jj < 4; jj++) s[i][jj] += a[i] * b[jj];
            }
            #pragma unroll
            for (int i = 0; i < 4; i++)
                #pragma unroll
                for (int jj = 0; jj < 4; jj++)
                    Ps[(ty*4+i)*65 + tx*4 + jj] = s[i][jj] * ATTN_SCALE;
        }
        __syncthreads();

        // Online softmax: 4 threads per row, 16 cols each
        {
            int row = tid >> 2, part = tid & 3;
            float* pr = Ps + row * 65 + part * 16;
            float mx = -INFINITY;
            #pragma unroll
            for (int c = 0; c < 16; c++) mx = fmaxf(mx, pr[c]);
            mx = fmaxf(mx, __shfl_xor_sync(0xffffffffu, mx, 1));
            mx = fmaxf(mx, __shfl_xor_sync(0xffffffffu, mx, 2));
            float mold = m_s[row];
            float mnew = fmaxf(mold, mx);
            float sum = 0.0f;
            #pragma unroll
            for (int c = 0; c < 16; c++) {
                float ev = __expf(pr[c] - mnew);
                pr[c] = ev;
                sum += ev;
            }
            sum += __shfl_xor_sync(0xffffffffu, sum, 1);
            sum += __shfl_xor_sync(0xffffffffu, sum, 2);
            if (part == 0) {
                float alpha = __expf(mold - mnew);   // 0 on first tile (mold=-inf)
                alpha_s[row] = alpha;
                l_s[row] = l_s[row] * alpha + sum;
                m_s[row] = mnew;
            }
        }
        __syncthreads();

        // acc = acc*alpha + P @ Vp
        {
            float al[4];
            #pragma unroll
            for (int i = 0; i < 4; i++) al[i] = alpha_s[ty*4 + i];
            #pragma unroll
            for (int i = 0; i < 4; i++)
                #pragma unroll
                for (int jj = 0; jj < 4; jj++) acc[i][jj] *= al[i];
            #pragma unroll
            for (int s = 0; s < 64; s++) {
                float a[4], b[4];
                #pragma unroll
                for (int i = 0; i < 4; i++) { a[i] = Ps[(ty*4+i)*65 + s]; b[i] = Vs[s*65 + tx*4 + i]; }
                #pragma unroll
                for (int i = 0; i < 4; i++)
                    #pragma unroll
                    for (int jj = 0; jj < 4; jj++) acc[i][jj] += a[i] * b[jj];
            }
        }
        __syncthreads();
    }

    // Epilogue: normalize, inverse GeM power, scatter to (L,N,E)
    int h = nh & 7, n = nh >> 3;
    #pragma unroll
    for (int i = 0; i < 4; i++) {
        int m = ty * 4 + i;
        float inv_l = 1.0f / l_s[m];
        int l = rowBase + m;
        #pragma unroll
        for (int jj = 0; jj < 4; jj++) {
            int d = tx * 4 + jj;
            int e = h * HD + d;
            float pooled = acc[i][jj] * inv_l;
            float o = powf(fmaxf(pooled, EPS), 1.0f / pp[e]) - shift[e];
            g_O[(size_t)(l * NB + n) * EM + e] = o;
        }
    }
}

// ---------------------------------------------------------------------------
// Kernel 3: output projection.  out = g_O @ Wout^T + b
// ---------------------------------------------------------------------------
__global__ __launch_bounds__(256) void outproj_kernel(
    const float* __restrict__ W, const float* __restrict__ bias,
    float* __restrict__ out)
{
    __shared__ float As[64][17];
    __shared__ float Bs[64][17];

    int tid = threadIdx.x;
    int tx = tid & 15, ty = tid >> 4;
    int rowBase = blockIdx.x * 64, colBase = blockIdx.y * 64;

    float acc[4][4] = {};

    for (int k0 = 0; k0 < EM; k0 += 16) {
        #pragma unroll
        for (int i = 0; i < 4; i++) {
            int idx = tid + i * 256;
            int m = idx >> 4, kk = idx & 15;
            As[m][kk] = g_O[(size_t)(rowBase + m) * EM + k0 + kk];
            Bs[m][kk] = W[(size_t)(colBase + m) * EM + k0 + kk];
        }
        __syncthreads();
        #pragma unroll
        for (int kk = 0; kk < 16; kk++) {
            float a[4], b[4];
            #pragma unroll
            for (int i = 0; i < 4; i++) { a[i] = As[ty*4+i][kk]; b[i] = Bs[tx*4+i][kk]; }
            #pragma unroll
            for (int i = 0; i < 4; i++)
                #pragma unroll
                for (int j = 0; j < 4; j++) acc[i][j] += a[i] * b[j];
        }
        __syncthreads();
    }

    #pragma unroll
    for (int i = 0; i < 4; i++) {
        int r = rowBase + ty * 4 + i;
        #pragma unroll
        for (int j = 0; j < 4; j++) {
            int e = colBase + tx * 4 + j;
            out[(size_t)r * EM + e] = acc[i][j] + bias[e];
        }
    }
}

// ---------------------------------------------------------------------------
extern "C" void kernel_launch(void* const* d_in, const int* in_sizes, int n_in,
                              void* d_out, int out_size)
{
    const float* query = (const float*)d_in[0];
    const float* keyi  = (const float*)d_in[1];
    const float* value = (const float*)d_in[2];
    const float* ipw   = (const float*)d_in[3];
    const float* ipb   = (const float*)d_in[4];
    const float* opw   = (const float*)d_in[5];
    const float* opb   = (const float*)d_in[6];
    const float* p     = (const float*)d_in[7];
    const float* shift = (const float*)d_in[8];
    float* out = (float*)d_out;

    // 1. Projections (q, k, v^p) -> (n,h,l,d)
    dim3 g1(RR / 64, EM / 64, 3);
    proj_kernel<<<g1, 256>>>(query, keyi, value, ipw, ipb, p, shift);

    // 2. Flash attention + GeM inverse power -> g_O in (L,N,E)
    int smem = 4 * 64 * 65 * (int)sizeof(float);   // 66,560 B
    cudaFuncSetAttribute(attn_kernel, cudaFuncAttributeMaxDynamicSharedMemorySize, smem);
    dim3 g2(L_SEQ / 64, NB * NH);
    attn_kernel<<<g2, 256, smem>>>(p, shift);

    // 3. Output projection -> d_out
    dim3 g3(RR / 64, EM / 64);
    outproj_kernel<<<g3, 256>>>(opw, opb, out);
}

// round 8
// speedup vs baseline: 1.3776x; 1.3776x over previous
#include <cuda_runtime.h>
#include <cuda_bf16.h>
#include <cstdint>
#include <math.h>

#define L_SEQ 2048
#define NB 4
#define EM 512
#define NH 8
#define HD 64
#define RR (L_SEQ*NB)       // 8192 rows
#define EPS 1e-6f
#define ATTN_SCALE 0.125f   // 1/sqrt(64)

// ---------------------------------------------------------------------------
// Scratch (device globals — no allocation allowed)
// ---------------------------------------------------------------------------
__device__ float g_Q[(size_t)NB*NH*L_SEQ*HD];   // (n,h,l,d)
__device__ float g_K[(size_t)NB*NH*L_SEQ*HD];
__device__ float g_Vp[(size_t)NB*NH*L_SEQ*HD];  // max(v+shift,eps)^p

// split-bf16 operands
__device__ __nv_bfloat16 g_Xh[3][(size_t)RR*EM];   // q/k/v inputs hi
__device__ __nv_bfloat16 g_Xl[3][(size_t)RR*EM];   // lo
__device__ __nv_bfloat16 g_Wh[3*EM*EM];            // in_proj weight hi
__device__ __nv_bfloat16 g_Wl[3*EM*EM];
__device__ __nv_bfloat16 g_Uh[EM*EM];              // out_proj weight hi
__device__ __nv_bfloat16 g_Ul[EM*EM];
__device__ __nv_bfloat16 g_Oh[(size_t)RR*EM];      // attention output hi (L,N,E)
__device__ __nv_bfloat16 g_Ol[(size_t)RR*EM];      // lo

// ---------------------------------------------------------------------------
// warp-MMA primitives (generic PTX, valid on compute_103 target)
// ---------------------------------------------------------------------------
__device__ __forceinline__ uint32_t smem_u32(const void* p) {
    uint32_t a;
    asm("{ .reg .u64 t; cvta.to.shared.u64 t, %1; cvt.u32.u64 %0, t; }" : "=r"(a) : "l"(p));
    return a;
}

__device__ __forceinline__ void ldsm_x4(uint32_t addr, uint32_t* r) {
    asm volatile("ldmatrix.sync.aligned.m8n8.x4.shared.b16 {%0,%1,%2,%3}, [%4];"
        : "=r"(r[0]), "=r"(r[1]), "=r"(r[2]), "=r"(r[3]) : "r"(addr));
}

__device__ __forceinline__ void mma16816(float* d, const uint32_t* a, uint32_t b0, uint32_t b1) {
    asm volatile("mma.sync.aligned.m16n8k16.row.col.f32.bf16.bf16.f32 "
        "{%0,%1,%2,%3}, {%4,%5,%6,%7}, {%8,%9}, {%0,%1,%2,%3};"
        : "+f"(d[0]), "+f"(d[1]), "+f"(d[2]), "+f"(d[3])
        : "r"(a[0]), "r"(a[1]), "r"(a[2]), "r"(a[3]), "r"(b0), "r"(b1));
}

// ---------------------------------------------------------------------------
// Split conversion kernels: fp32 -> (bf16 hi, bf16 lo)
// ---------------------------------------------------------------------------
__device__ __forceinline__ void split4(float4 x, __nv_bfloat16* h, __nv_bfloat16* l) {
    h[0] = __float2bfloat16(x.x); l[0] = __float2bfloat16(x.x - __bfloat162float(h[0]));
    h[1] = __float2bfloat16(x.y); l[1] = __float2bfloat16(x.y - __bfloat162float(h[1]));
    h[2] = __float2bfloat16(x.z); l[2] = __float2bfloat16(x.z - __bfloat162float(h[2]));
    h[3] = __float2bfloat16(x.w); l[3] = __float2bfloat16(x.w - __bfloat162float(h[3]));
}

__global__ __launch_bounds__(256) void conv_x_kernel(
    const float* __restrict__ q, const float* __restrict__ k, const float* __restrict__ v)
{
    int z = blockIdx.y;
    const float* src = (z == 0) ? q : (z == 1) ? k : v;
    size_t i = ((size_t)blockIdx.x * 256 + threadIdx.x) * 4;
    float4 x = *(const float4*)(src + i);
    __nv_bfloat16 h[4], l[4];
    split4(x, h, l);
    *(uint2*)(&g_Xh[z][i]) = *(uint2*)h;
    *(uint2*)(&g_Xl[z][i]) = *(uint2*)l;
}

__global__ __launch_bounds__(256) void conv_w_kernel(
    const float* __restrict__ ipw, const float* __restrict__ opw)
{
    size_t i = ((size_t)blockIdx.x * 256 + threadIdx.x) * 4;
    __nv_bfloat16 h[4], l[4];
    if (i < (size_t)3 * EM * EM) {
        split4(*(const float4*)(ipw + i), h, l);
        *(uint2*)(&g_Wh[i]) = *(uint2*)h;
        *(uint2*)(&g_Wl[i]) = *(uint2*)l;
    } else {
        size_t j = i - (size_t)3 * EM * EM;
        split4(*(const float4*)(opw + j), h, l);
        *(uint2*)(&g_Uh[j]) = *(uint2*)h;
        *(uint2*)(&g_Ul[j]) = *(uint2*)l;
    }
}

// ---------------------------------------------------------------------------
// Shared warp-MMA mainloop: acc[128x128 per CTA] += sum of 3 split passes of
// A[128xK] * B[128xK]^T, K = 512.  8 warps in 2(m) x 4(n), 64x32 per warp.
// smem tiles 128x64 bf16, SW128 XOR swizzle, ldmatrix fragments.
// ---------------------------------------------------------------------------
__device__ __forceinline__ void wmma_mainloop(
    const __nv_bfloat16* __restrict__ Ah, const __nv_bfloat16* __restrict__ Al,
    const __nv_bfloat16* __restrict__ Bh, const __nv_bfloat16* __restrict__ Bl,
    int rowBase, int colBase, char* smA, char* smB,
    uint32_t smA_u, uint32_t smB_u, int tid, float acc[4][4][4])
{
    int lane = tid & 31, wid = tid >> 5;
    int wm = wid & 1, wn = wid >> 1;

    for (int p = 0; p < 3; p++) {
        const __nv_bfloat16* As = (p < 2) ? Ah : Al;   // hi*hi, hi*lo, lo*hi
        const __nv_bfloat16* Bs = (p == 1) ? Bl : Bh;
        for (int kc = 0; kc < EM; kc += 64) {
            // global -> smem, 128 rows x 64 bf16 (128 B/row), swizzled
            #pragma unroll
            for (int i = 0; i < 4; i++) {
                int c = tid + i * 256;
                int r = c >> 3, ch = c & 7;
                uint32_t off = (uint32_t)(r * 128 + ch * 16);
                uint32_t sw = off ^ ((off >> 3) & 0x70);
                *(uint4*)(smA + sw) = *(const uint4*)(As + (size_t)(rowBase + r) * EM + kc + ch * 8);
                *(uint4*)(smB + sw) = *(const uint4*)(Bs + (size_t)(colBase + r) * EM + kc + ch * 8);
            }
            __syncthreads();

            #pragma unroll
            for (int ks = 0; ks < 4; ks++) {
                // A fragments: 4 m16 tiles
                uint32_t afr[4][4];
                #pragma unroll
                for (int mt = 0; mt < 4; mt++) {
                    int row = wm * 64 + mt * 16 + (lane & 15);
                    uint32_t off = (uint32_t)(row * 128 + ks * 32 + (lane >> 4) * 16);
                    uint32_t sw = off ^ ((off >> 3) & 0x70);
                    ldsm_x4(smA_u + sw, afr[mt]);
                }
                // B fragments: 2 x (16 n-rows x k16) -> 4 n8 tiles
                uint32_t bfr[2][4];
                #pragma unroll
                for (int bt = 0; bt < 2; bt++) {
                    int row = wn * 32 + bt * 16 + (lane & 15);
                    uint32_t off = (uint32_t)(row * 128 + ks * 32 + (lane >> 4) * 16);
                    uint32_t sw = off ^ ((off >> 3) & 0x70);
                    ldsm_x4(smB_u + sw, bfr[bt]);
                }
                #pragma unroll
                for (int mt = 0; mt < 4; mt++)
                    #pragma unroll
                    for (int nt = 0; nt < 4; nt++)
                        mma16816(acc[mt][nt], afr[mt],
                                 bfr[nt >> 1][nt & 1], bfr[nt >> 1][(nt & 1) + 2]);
            }
            __syncthreads();
        }
    }
}

// ---------------------------------------------------------------------------
// Kernel 1: QKV projection (warp MMA).  Epilogue: +bias, scatter (n,h,l,d),
// GeM forward power for v.  grid (64, 4, 3), 256 threads.
// ---------------------------------------------------------------------------
__global__ __launch_bounds__(256) void proj_mma_kernel(
    const float* __restrict__ bias,
    const float* __restrict__ pp, const float* __restrict__ shift)
{
    __shared__ __align__(128) char smA[128 * 128];
    __shared__ __align__(128) char smB[128 * 128];

    int z = blockIdx.z;
    int rowBase = blockIdx.x * 128, colBase = blockIdx.y * 128;
    int tid = threadIdx.x, lane = tid & 31, wid = tid >> 5;
    int wm = wid & 1, wn = wid >> 1;

    float acc[4][4][4] = {};
    wmma_mainloop(g_Xh[z], g_Xl[z], g_Wh + (size_t)z * EM * EM, g_Wl + (size_t)z * EM * EM,
                  rowBase, colBase, smA, smB, smem_u32(smA), smem_u32(smB), tid, acc);

    float* dst = (z == 0) ? g_Q : (z == 1) ? g_K : g_Vp;
    int r0 = rowBase + wm * 64;
    int c0 = colBase + wn * 32;
    #pragma unroll
    for (int mt = 0; mt < 4; mt++) {
        #pragma unroll
        for (int rr = 0; rr < 2; rr++) {
            int r = r0 + mt * 16 + (lane >> 2) + rr * 8;
            int l = r >> 2, n = r & 3;           // r = l*NB + n
            #pragma unroll
            for (int nt = 0; nt < 4; nt++) {
                int e = c0 + nt * 8 + (lane & 3) * 2;
                float v0 = acc[mt][nt][rr * 2 + 0] + bias[z * EM + e];
                float v1 = acc[mt][nt][rr * 2 + 1] + bias[z * EM + e + 1];
                if (z == 2) {
                    v0 = powf(fmaxf(v0 + shift[e],     EPS), pp[e]);
                    v1 = powf(fmaxf(v1 + shift[e + 1], EPS), pp[e + 1]);
                }
                int h = e >> 6, d = e & 63;
                *(float2*)(dst + ((size_t)(n * NH + h) * L_SEQ + l) * HD + d)
                    = make_float2(v0, v1);
            }
        }
    }
}

// ---------------------------------------------------------------------------
// Kernel 3: output projection (warp MMA).  out = O @ Wout^T + b.
// grid (64, 4), 256 threads.
// ---------------------------------------------------------------------------
__global__ __launch_bounds__(256) void outp_mma_kernel(
    const float* __restrict__ bias, float* __restrict__ out)
{
    __shared__ __align__(128) char smA[128 * 128];
    __shared__ __align__(128) char smB[128 * 128];

    int rowBase = blockIdx.x * 128, colBase = blockIdx.y * 128;
    int tid = threadIdx.x, lane = tid & 31, wid = tid >> 5;
    int wm = wid & 1, wn = wid >> 1;

    float acc[4][4][4] = {};
    wmma_mainloop(g_Oh, g_Ol, g_Uh, g_Ul,
                  rowBase, colBase, smA, smB, smem_u32(smA), smem_u32(smB), tid, acc);

    int r0 = rowBase + wm * 64;
    int c0 = colBase + wn * 32;
    #pragma unroll
    for (int mt = 0; mt < 4; mt++) {
        #pragma unroll
        for (int rr = 0; rr < 2; rr++) {
            int r = r0 + mt * 16 + (lane >> 2) + rr * 8;
            #pragma unroll
            for (int nt = 0; nt < 4; nt++) {
                int e = c0 + nt * 8 + (lane & 3) * 2;
                float v0 = acc[mt][nt][rr * 2 + 0] + bias[e];
                float v1 = acc[mt][nt][rr * 2 + 1] + bias[e + 1];
                *(float2*)(out + (size_t)r * EM + e) = make_float2(v0, v1);
            }
        }
    }
}

// ---------------------------------------------------------------------------
// Kernel 2: flash attention (fp32, proven) + GeM inverse power.
// Epilogue now emits split-bf16 O directly (g_Oh/g_Ol).
// ---------------------------------------------------------------------------
__global__ __launch_bounds__(256) void attn_kernel(
    const float* __restrict__ pp, const float* __restrict__ shift)
{
    extern __shared__ float sm[];
    float* Qs = sm;                 // 64 x 65
    float* Ks = sm + 64 * 65;
    float* Vs = sm + 2 * 64 * 65;
    float* Ps = sm + 3 * 64 * 65;
    __shared__ float m_s[64], l_s[64], alpha_s[64];

    int nh = blockIdx.y;
    int rowBase = blockIdx.x * 64;
    const float* Qb = g_Q  + (size_t)nh * L_SEQ * HD;
    const float* Kb = g_K  + (size_t)nh * L_SEQ * HD;
    const float* Vb = g_Vp + (size_t)nh * L_SEQ * HD;

    int tid = threadIdx.x;
    int tx = tid & 15, ty = tid >> 4;

    #pragma unroll
    for (int i = 0; i < 16; i++) {
        int idx = tid + i * 256;
        int m = idx >> 6, d = idx & 63;
        Qs[m * 65 + d] = Qb[(size_t)(rowBase + m) * HD + d];
    }
    if (tid < 64) { m_s[tid] = -INFINITY; l_s[tid] = 0.0f; }

    float acc[4][4] = {};
    __syncthreads();

    for (int j0 = 0; j0 < L_SEQ; j0 += 64) {
        #pragma unroll
        for (int i = 0; i < 16; i++) {
            int idx = tid + i * 256;
            int m = idx >> 6, d = idx & 63;
            Ks[m * 65 + d] = Kb[(size_t)(j0 + m) * HD + d];
            Vs[m * 65 + d] = Vb[(size_t)(j0 + m) * HD + d];
        }
        __syncthreads();

        {
            float s[4][4] = {};
            #pragma unroll
            for (int k = 0; k < 64; k++) {
                float a[4], b[4];
                #pragma unroll
                for (int i = 0; i < 4; i++) { a[i] = Qs[(ty*4+i)*65 + k]; b[i] = Ks[(tx*4+i)*65 + k]; }
                #pragma unroll
                for (int i = 0; i < 4; i++)
                    #pragma unroll
                    for (int jj = 0; jj < 4; jj++) s[i][jj] += a[i] * b[jj];
            }
            #pragma unroll
            for (int i = 0; i < 4; i++)
                #pragma unroll
                for (int jj = 0; jj < 4; jj++)
                    Ps[(ty*4+i)*65 + tx*4 + jj] = s[i][jj] * ATTN_SCALE;
        }
        __syncthreads();

        {
            int row = tid >> 2, part = tid & 3;
            float* pr = Ps + row * 65 + part * 16;
            float mx = -INFINITY;
            #pragma unroll
            for (int c = 0; c < 16; c++) mx = fmaxf(mx, pr[c]);
            mx = fmaxf(mx, __shfl_xor_sync(0xffffffffu, mx, 1));
            mx = fmaxf(mx, __shfl_xor_sync(0xffffffffu, mx, 2));
            float mold = m_s[row];
            float mnew = fmaxf(mold, mx);
            float sum = 0.0f;
            #pragma unroll
            for (int c = 0; c < 16; c++) {
                float ev = __expf(pr[c] - mnew);
                pr[c] = ev;
                sum += ev;
            }
            sum += __shfl_xor_sync(0xffffffffu, sum, 1);
            sum += __shfl_xor_sync(0xffffffffu, sum, 2);
            if (part == 0) {
                float alpha = __expf(mold - mnew);
                alpha_s[row] = alpha;
                l_s[row] = l_s[row] * alpha + sum;
                m_s[row] = mnew;
            }
        }
        __syncthreads();

        {
            float al[4];
            #pragma unroll
            for (int i = 0; i < 4; i++) al[i] = alpha_s[ty*4 + i];
            #pragma unroll
            for (int i = 0; i < 4; i++)
                #pragma unroll
                for (int jj = 0; jj < 4; jj++) acc[i][jj] *= al[i];
            #pragma unroll
            for (int s = 0; s < 64; s++) {
                float a[4], b[4];
                #pragma unroll
                for (int i = 0; i < 4; i++) { a[i] = Ps[(ty*4+i)*65 + s]; b[i] = Vs[s*65 + tx*4 + i]; }
                #pragma unroll
                for (int i = 0; i < 4; i++)
                    #pragma unroll
                    for (int jj = 0; jj < 4; jj++) acc[i][jj] += a[i] * b[jj];
            }
        }
        __syncthreads();
    }

    int h = nh & 7, n = nh >> 3;
    #pragma unroll
    for (int i = 0; i < 4; i++) {
        int m = ty * 4 + i;
        float inv_l = 1.0f / l_s[m];
        int l = rowBase + m;
        #pragma unroll
        for (int jj = 0; jj < 4; jj++) {
            int d = tx * 4 + jj;
            int e = h * HD + d;
            float pooled = acc[i][jj] * inv_l;
            float o = powf(fmaxf(pooled, EPS), 1.0f / pp[e]) - shift[e];
            size_t idx = (size_t)(l * NB + n) * EM + e;
            __nv_bfloat16 oh = __float2bfloat16(o);
            g_Oh[idx] = oh;
            g_Ol[idx] = __float2bfloat16(o - __bfloat162float(oh));
        }
    }
}

// ---------------------------------------------------------------------------
extern "C" void kernel_launch(void* const* d_in, const int* in_sizes, int n_in,
                              void* d_out, int out_size)
{
    const float* query = (const float*)d_in[0];
    const float* keyi  = (const float*)d_in[1];
    const float* value = (const float*)d_in[2];
    const float* ipw   = (const float*)d_in[3];
    const float* ipb   = (const float*)d_in[4];
    const float* opw   = (const float*)d_in[5];
    const float* opb   = (const float*)d_in[6];
    const float* p     = (const float*)d_in[7];
    const float* shift = (const float*)d_in[8];
    float* out = (float*)d_out;

    // 0. split-bf16 conversions
    conv_x_kernel<<<dim3((RR * EM) / 1024, 3), 256>>>(query, keyi, value);
    conv_w_kernel<<<(4 * EM * EM) / 1024, 256>>>(ipw, opw);

    // 1. QKV projection (HMMA split-bf16) -> g_Q / g_K / g_Vp
    proj_mma_kernel<<<dim3(RR / 128, EM / 128, 3), 256>>>(ipb, p, shift);

    // 2. Flash attention (fp32) + GeM inverse power -> g_Oh / g_Ol
    int smem = 4 * 64 * 65 * (int)sizeof(float);
    cudaFuncSetAttribute(attn_kernel, cudaFuncAttributeMaxDynamicSharedMemorySize, smem);
    attn_kernel<<<dim3(L_SEQ / 64, NB * NH), 256, smem>>>(p, shift);

    // 3. Output projection (HMMA split-bf16) -> d_out
    outp_mma_kernel<<<dim3(RR / 128, EM / 128), 256>>>(opb, out);
}

// round 14
// speedup vs baseline: 2.4175x; 1.7549x over previous
#include <cuda_runtime.h>
#include <cuda_bf16.h>
#include <cstdint>
#include <math.h>

#define L_SEQ 2048
#define NB 4
#define EM 512
#define NH 8
#define HD 64
#define RR (L_SEQ*NB)       // 8192 rows
#define EPS 1e-6f
// fold 1/sqrt(64) * log2(e) into Q so softmax runs in exp2 domain
#define QSCALE 0.1803368801111204f

// ---------------------------------------------------------------------------
// Scratch (device globals — no allocation allowed)
// ---------------------------------------------------------------------------
// split-bf16 Q/K/Vc in (n,h,l,d);  Vc = max(v+shift,EPS)^p - C_e  (centered)
__device__ __nv_bfloat16 g_Qh[(size_t)NB*NH*L_SEQ*HD];
__device__ __nv_bfloat16 g_Ql[(size_t)NB*NH*L_SEQ*HD];
__device__ __nv_bfloat16 g_Kh[(size_t)NB*NH*L_SEQ*HD];
__device__ __nv_bfloat16 g_Kl[(size_t)NB*NH*L_SEQ*HD];
__device__ __nv_bfloat16 g_Vh[(size_t)NB*NH*L_SEQ*HD];
__device__ __nv_bfloat16 g_Vl[(size_t)NB*NH*L_SEQ*HD];

// split-bf16 GEMM operands
__device__ __nv_bfloat16 g_Xh[3][(size_t)RR*EM];   // q/k/v inputs hi
__device__ __nv_bfloat16 g_Xl[3][(size_t)RR*EM];   // lo
__device__ __nv_bfloat16 g_Wh[3*EM*EM];            // in_proj weight hi
__device__ __nv_bfloat16 g_Wl[3*EM*EM];
__device__ __nv_bfloat16 g_Uh[EM*EM];              // out_proj weight hi
__device__ __nv_bfloat16 g_Ul[EM*EM];
__device__ __nv_bfloat16 g_Oh[(size_t)RR*EM];      // attention output hi (L,N,E)
__device__ __nv_bfloat16 g_Ol[(size_t)RR*EM];      // lo

// ---------------------------------------------------------------------------
// warp-MMA primitives (generic PTX, valid on compute_103 target)
// ---------------------------------------------------------------------------
__device__ __forceinline__ uint32_t smem_u32(const void* p) {
    uint32_t a;
    asm("{ .reg .u64 t; cvta.to.shared.u64 t, %1; cvt.u32.u64 %0, t; }" : "=r"(a) : "l"(p));
    return a;
}
__device__ __forceinline__ void ldsm_x4(uint32_t addr, uint32_t* r) {
    asm volatile("ldmatrix.sync.aligned.m8n8.x4.shared.b16 {%0,%1,%2,%3}, [%4];"
        : "=r"(r[0]), "=r"(r[1]), "=r"(r[2]), "=r"(r[3]) : "r"(addr));
}
__device__ __forceinline__ void ldsm_x4_t(uint32_t addr, uint32_t* r) {
    asm volatile("ldmatrix.sync.aligned.m8n8.x4.trans.shared.b16 {%0,%1,%2,%3}, [%4];"
        : "=r"(r[0]), "=r"(r[1]), "=r"(r[2]), "=r"(r[3]) : "r"(addr));
}
__device__ __forceinline__ void mma16816(float* d, const uint32_t* a, uint32_t b0, uint32_t b1) {
    asm volatile("mma.sync.aligned.m16n8k16.row.col.f32.bf16.bf16.f32 "
        "{%0,%1,%2,%3}, {%4,%5,%6,%7}, {%8,%9}, {%0,%1,%2,%3};"
        : "+f"(d[0]), "+f"(d[1]), "+f"(d[2]), "+f"(d[3])
        : "r"(a[0]), "r"(a[1]), "r"(a[2]), "r"(a[3]), "r"(b0), "r"(b1));
}
__device__ __forceinline__ void cp16(uint32_t dst, const void* src) {
    asm volatile("cp.async.cg.shared.global [%0], [%1], 16;" :: "r"(dst), "l"(src));
}
#define CP_COMMIT() asm volatile("cp.async.commit_group;" ::: "memory")
#define CP_WAIT1()  asm volatile("cp.async.wait_group 1;" ::: "memory")
#define CP_WAIT0()  asm volatile("cp.async.wait_group 0;" ::: "memory")

__device__ __forceinline__ uint32_t swz(uint32_t off) { return off ^ ((off >> 3) & 0x70); }

// FMA-pipe exp2, degree-7 Taylor: |rel err| ~5e-9, no MUFU.
__device__ __forceinline__ float fast_exp2(float x) {
    x = fmaxf(x, -126.0f);
    float t = x + 12582912.0f;                  // round-to-nearest integer trick
    int   n = __float_as_int(t) - 0x4B400000;
    float f = x - (t - 12582912.0f);            // f in [-0.5, 0.5]
    float p = 1.5252734e-5f;
    p = fmaf(p, f, 1.5403530e-4f);
    p = fmaf(p, f, 1.3333558e-3f);
    p = fmaf(p, f, 9.6181291e-3f);
    p = fmaf(p, f, 5.5504109e-2f);
    p = fmaf(p, f, 2.4022651e-1f);
    p = fmaf(p, f, 6.9314718e-1f);
    p = fmaf(p, f, 1.0f);
    return p * __int_as_float((n + 127) << 23);
}

__device__ __forceinline__ uint32_t pack2(float a, float b) {
    __nv_bfloat162 h = __floats2bfloat162_rn(a, b);
    return *(uint32_t*)&h;
}

// ---------------------------------------------------------------------------
// Split conversion kernels: fp32 -> (bf16 hi, bf16 lo)
// ---------------------------------------------------------------------------
__device__ __forceinline__ void split4(float4 x, __nv_bfloat16* h, __nv_bfloat16* l) {
    h[0] = __float2bfloat16(x.x); l[0] = __float2bfloat16(x.x - __bfloat162float(h[0]));
    h[1] = __float2bfloat16(x.y); l[1] = __float2bfloat16(x.y - __bfloat162float(h[1]));
    h[2] = __float2bfloat16(x.z); l[2] = __float2bfloat16(x.z - __bfloat162float(h[2]));
    h[3] = __float2bfloat16(x.w); l[3] = __float2bfloat16(x.w - __bfloat162float(h[3]));
}

__global__ __launch_bounds__(256) void conv_x_kernel(
    const float* __restrict__ q, const float* __restrict__ k, const float* __restrict__ v)
{
    int z = blockIdx.y;
    const float* src = (z == 0) ? q : (z == 1) ? k : v;
    size_t i = ((size_t)blockIdx.x * 256 + threadIdx.x) * 4;
    float4 x = *(const float4*)(src + i);
    __nv_bfloat16 h[4], l[4];
    split4(x, h, l);
    *(uint2*)(&g_Xh[z][i]) = *(uint2*)h;
    *(uint2*)(&g_Xl[z][i]) = *(uint2*)l;
}

__global__ __launch_bounds__(256) void conv_w_kernel(
    const float* __restrict__ ipw, const float* __restrict__ opw)
{
    size_t i = ((size_t)blockIdx.x * 256 + threadIdx.x) * 4;
    __nv_bfloat16 h[4], l[4];
    if (i < (size_t)3 * EM * EM) {
        split4(*(const float4*)(ipw + i), h, l);
        *(uint2*)(&g_Wh[i]) = *(uint2*)h;
        *(uint2*)(&g_Wl[i]) = *(uint2*)l;
    } else {
        size_t j = i - (size_t)3 * EM * EM;
        split4(*(const float4*)(opw + j), h, l);
        *(uint2*)(&g_Uh[j]) = *(uint2*)h;
        *(uint2*)(&g_Ul[j]) = *(uint2*)l;
    }
}

// ---------------------------------------------------------------------------
// Shared warp-MMA mainloop (proven R8): acc += 3 split passes of A*B^T, K=512.
// ---------------------------------------------------------------------------
__device__ __forceinline__ void wmma_mainloop(
    const __nv_bfloat16* __restrict__ Ah, const __nv_bfloat16* __restrict__ Al,
    const __nv_bfloat16* __restrict__ Bh, const __nv_bfloat16* __restrict__ Bl,
    int rowBase, int colBase, char* smA, char* smB,
    uint32_t smA_u, uint32_t smB_u, int tid, float acc[4][4][4])
{
    int lane = tid & 31, wid = tid >> 5;
    int wm = wid & 1, wn = wid >> 1;

    for (int p = 0; p < 3; p++) {
        const __nv_bfloat16* As = (p < 2) ? Ah : Al;   // hi*hi, hi*lo, lo*hi
        const __nv_bfloat16* Bs = (p == 1) ? Bl : Bh;
        for (int kc = 0; kc < EM; kc += 64) {
            #pragma unroll
            for (int i = 0; i < 4; i++) {
                int c = tid + i * 256;
                int r = c >> 3, ch = c & 7;
                uint32_t sw = swz((uint32_t)(r * 128 + ch * 16));
                *(uint4*)(smA + sw) = *(const uint4*)(As + (size_t)(rowBase + r) * EM + kc + ch * 8);
                *(uint4*)(smB + sw) = *(const uint4*)(Bs + (size_t)(colBase + r) * EM + kc + ch * 8);
            }
            __syncthreads();

            #pragma unroll
            for (int ks = 0; ks < 4; ks++) {
                uint32_t afr[4][4];
                #pragma unroll
                for (int mt = 0; mt < 4; mt++) {
                    int row = wm * 64 + mt * 16 + (lane & 15);
                    ldsm_x4(smA_u + swz((uint32_t)(row * 128 + ks * 32 + (lane >> 4) * 16)), afr[mt]);
                }
                uint32_t bfr[2][4];
                #pragma unroll
                for (int bt = 0; bt < 2; bt++) {
                    int row = wn * 32 + bt * 16 + (lane & 15);
                    ldsm_x4(smB_u + swz((uint32_t)(row * 128 + ks * 32 + (lane >> 4) * 16)), bfr[bt]);
                }
                #pragma unroll
                for (int mt = 0; mt < 4; mt++)
                    #pragma unroll
                    for (int nt = 0; nt < 4; nt++)
                        mma16816(acc[mt][nt], afr[mt],
                                 bfr[nt >> 1][nt & 1], bfr[nt >> 1][(nt & 1) + 2]);
            }
            __syncthreads();
        }
    }
}

// ---------------------------------------------------------------------------
// Kernel 1: QKV projection.  Epilogue: +bias; z=0: fold QSCALE into Q;
// z=2: GeM forward power, then center by C_e = shift^p; split-bf16 scatter
// to (n,h,l,d).  grid (64, 4, 3), 256 threads.
// ---------------------------------------------------------------------------
__global__ __launch_bounds__(256) void proj_mma_kernel(
    const float* __restrict__ bias,
    const float* __restrict__ pp, const float* __restrict__ shift)
{
    __shared__ __align__(128) char smA[128 * 128];
    __shared__ __align__(128) char smB[128 * 128];

    int z = blockIdx.z;
    int rowBase = blockIdx.x * 128, colBase = blockIdx.y * 128;
    int tid = threadIdx.x, lane = tid & 31, wid = tid >> 5;
    int wm = wid & 1, wn = wid >> 1;

    float acc[4][4][4] = {};
    wmma_mainloop(g_Xh[z], g_Xl[z], g_Wh + (size_t)z * EM * EM, g_Wl + (size_t)z * EM * EM,
                  rowBase, colBase, smA, smB, smem_u32(smA), smem_u32(smB), tid, acc);

    __nv_bfloat16* dstH = (z == 0) ? g_Qh : (z == 1) ? g_Kh : g_Vh;
    __nv_bfloat16* dstL = (z == 0) ? g_Ql : (z == 1) ? g_Kl : g_Vl;
    int r0 = rowBase + wm * 64;
    int c0 = colBase + wn * 32;
    #pragma unroll
    for (int mt = 0; mt < 4; mt++) {
        #pragma unroll
        for (int rr = 0; rr < 2; rr++) {
            int r = r0 + mt * 16 + (lane >> 2) + rr * 8;
            int l = r >> 2, n = r & 3;           // r = l*NB + n
            #pragma unroll
            for (int nt = 0; nt < 4; nt++) {
                int e = c0 + nt * 8 + (lane & 3) * 2;
                float v0 = acc[mt][nt][rr * 2 + 0] + bias[z * EM + e];
                float v1 = acc[mt][nt][rr * 2 + 1] + bias[z * EM + e + 1];
                if (z == 0) { v0 *= QSCALE; v1 *= QSCALE; }
                if (z == 2) {
                    // centered GeM power: Vc = max(v+shift,EPS)^p - shift^p
                    v0 = powf(fmaxf(v0 + shift[e],     EPS), pp[e])     - powf(shift[e],     pp[e]);
                    v1 = powf(fmaxf(v1 + shift[e + 1], EPS), pp[e + 1]) - powf(shift[e + 1], pp[e + 1]);
                }
                __nv_bfloat16 h0 = __float2bfloat16(v0);
                __nv_bfloat16 h1 = __float2bfloat16(v1);
                float l0 = v0 - __bfloat162float(h0);
                float l1 = v1 - __bfloat162float(h1);
                int hh = e >> 6, d = e & 63;
                size_t idx = ((size_t)(n * NH + hh) * L_SEQ + l) * HD + d;
                uint32_t hp; { __nv_bfloat162 t2 = __nv_bfloat162(h0, h1); hp = *(uint32_t*)&t2; }
                *(uint32_t*)(dstH + idx) = hp;
                *(uint32_t*)(dstL + idx) = pack2(l0, l1);
            }
        }
    }
}

// ---------------------------------------------------------------------------
// Kernel 3: output projection.  out = O @ Wout^T + b.  grid (64, 4), 256 thr.
// ---------------------------------------------------------------------------
__global__ __launch_bounds__(256) void outp_mma_kernel(
    const float* __restrict__ bias, float* __restrict__ out)
{
    __shared__ __align__(128) char smA[128 * 128];
    __shared__ __align__(128) char smB[128 * 128];

    int rowBase = blockIdx.x * 128, colBase = blockIdx.y * 128;
    int tid = threadIdx.x, lane = tid & 31, wid = tid >> 5;
    int wm = wid & 1, wn = wid >> 1;

    float acc[4][4][4] = {};
    wmma_mainloop(g_Oh, g_Ol, g_Uh, g_Ul,
                  rowBase, colBase, smA, smB, smem_u32(smA), smem_u32(smB), tid, acc);

    int r0 = rowBase + wm * 64;
    int c0 = colBase + wn * 32;
    #pragma unroll
    for (int mt = 0; mt < 4; mt++) {
        #pragma unroll
        for (int rr = 0; rr < 2; rr++) {
            int r = r0 + mt * 16 + (lane >> 2) + rr * 8;
            #pragma unroll
            for (int nt = 0; nt < 4; nt++) {
                int e = c0 + nt * 8 + (lane & 3) * 2;
                float v0 = acc[mt][nt][rr * 2 + 0] + bias[e];
                float v1 = acc[mt][nt][rr * 2 + 1] + bias[e + 1];
                *(float2*)(out + (size_t)r * EM + e) = make_float2(v0, v1);
            }
        }
    }
}

// ---------------------------------------------------------------------------
// Kernel 2: FA2-style flash attention with mma.sync, split-bf16 QK and PV
// (FULL 4-pass: hh + hl + lh + ll), FMA-pipe exp2 softmax, cp.async
// double-buffered KV, centered-V reconstruction in epilogue.
// CTA: 128 Q rows, 8 warps (m16 each).  KV tiles of 64.
// smem: Qh 16K | Ql 16K | 2 x [Kh 8K | Kl 8K | Vh 8K | Vl 8K]  = 96 KB.
// ---------------------------------------------------------------------------
#define SM_QH 0
#define SM_QL 16384
#define SM_KV 32768
#define KV_STRIDE 32768

__global__ __launch_bounds__(256) void attn_mma_kernel(
    const float* __restrict__ pp, const float* __restrict__ shift)
{
    extern __shared__ char sm[];
    uint32_t sm_u = smem_u32(sm);

    int nh = blockIdx.y;                 // n*NH + h
    int rowBase = blockIdx.x * 128;
    int tid = threadIdx.x, lane = tid & 31, wid = tid >> 5;

    const __nv_bfloat16* Qh = g_Qh + (size_t)nh * L_SEQ * HD;
    const __nv_bfloat16* Ql = g_Ql + (size_t)nh * L_SEQ * HD;
    const __nv_bfloat16* Kh = g_Kh + (size_t)nh * L_SEQ * HD;
    const __nv_bfloat16* Kl = g_Kl + (size_t)nh * L_SEQ * HD;
    const __nv_bfloat16* Vh = g_Vh + (size_t)nh * L_SEQ * HD;
    const __nv_bfloat16* Vl = g_Vl + (size_t)nh * L_SEQ * HD;

    // ---- issue Q staging (2048 x 16B chunks) ----
    #pragma unroll
    for (int i = 0; i < 8; i++) {
        int c = tid + i * 256;
        int arr = c >> 10, cc = c & 1023;
        int row = cc >> 3, ch = cc & 7;
        const __nv_bfloat16* src = arr ? Ql : Qh;
        cp16(sm_u + (arr ? SM_QL : SM_QH) + swz((uint32_t)(row * 128 + ch * 16)),
             src + (size_t)(rowBase + row) * HD + ch * 8);
    }
    CP_COMMIT();

    // ---- issue KV tile 0 ----
    {
        #pragma unroll
        for (int i = 0; i < 8; i++) {
            int c = tid + i * 256;
            int arr = c >> 9, cc = c & 511;
            int row = cc >> 3, ch = cc & 7;
            const __nv_bfloat16* src = (arr == 0) ? Kh : (arr == 1) ? Kl : (arr == 2) ? Vh : Vl;
            cp16(sm_u + SM_KV + arr * 8192 + swz((uint32_t)(row * 128 + ch * 16)),
                 src + (size_t)row * HD + ch * 8);
        }
        CP_COMMIT();
    }

    CP_WAIT1();          // Q staged
    __syncthreads();

    // ---- extract Q fragments once (hi + lo) ----
    uint32_t aqh[4][4], aql[4][4];
    #pragma unroll
    for (int ks = 0; ks < 4; ks++) {
        uint32_t off = (uint32_t)((wid * 16 + (lane & 15)) * 128 + (ks * 2 + (lane >> 4)) * 16);
        ldsm_x4(sm_u + SM_QH + swz(off), aqh[ks]);
        ldsm_x4(sm_u + SM_QL + swz(off), aql[ks]);
    }

    float oacc[8][4] = {};
    float m_lo = -1e30f, m_hi = -1e30f, l_lo = 0.0f, l_hi = 0.0f;

    for (int j = 0; j < L_SEQ / 64; j++) {
        uint32_t buf = sm_u + SM_KV + (uint32_t)(j & 1) * KV_STRIDE;

        if (j + 1 < L_SEQ / 64) {
            uint32_t nbuf = sm_u + SM_KV + (uint32_t)((j + 1) & 1) * KV_STRIDE;
            #pragma unroll
            for (int i = 0; i < 8; i++) {
                int c = tid + i * 256;
                int arr = c >> 9, cc = c & 511;
                int row = cc >> 3, ch = cc & 7;
                const __nv_bfloat16* src = (arr == 0) ? Kh : (arr == 1) ? Kl : (arr == 2) ? Vh : Vl;
                cp16(nbuf + arr * 8192 + swz((uint32_t)(row * 128 + ch * 16)),
                     src + (size_t)((j + 1) * 64 + row) * HD + ch * 8);
            }
            CP_COMMIT();
            CP_WAIT1();
        } else {
            CP_WAIT0();
        }
        __syncthreads();

        // ---- S = Q K^T (exp2 domain; QSCALE folded into Q), FULL 4-pass ----
        float sacc[8][4] = {};
        #pragma unroll
        for (int ks = 0; ks < 4; ks++) {
            #pragma unroll
            for (int st = 0; st < 4; st++) {
                uint32_t off = swz((uint32_t)((st * 16 + (lane & 15)) * 128 + (ks * 2 + (lane >> 4)) * 16));
                uint32_t bh[4], bl[4];
                ldsm_x4(buf + 0    + off, bh);   // Kh
                ldsm_x4(buf + 8192 + off, bl);   // Kl
                mma16816(sacc[st * 2],     aqh[ks], bh[0], bh[2]);
                mma16816(sacc[st * 2 + 1], aqh[ks], bh[1], bh[3]);
                mma16816(sacc[st * 2],     aqh[ks], bl[0], bl[2]);
                mma16816(sacc[st * 2 + 1], aqh[ks], bl[1], bl[3]);
                mma16816(sacc[st * 2],     aql[ks], bh[0], bh[2]);
                mma16816(sacc[st * 2 + 1], aql[ks], bh[1], bh[3]);
                mma16816(sacc[st * 2],     aql[ks], bl[0], bl[2]);
                mma16816(sacc[st * 2 + 1], aql[ks], bl[1], bl[3]);
            }
        }

        // ---- online softmax (exp2 domain, FMA pipe) ----
        float tmx_lo = -1e30f, tmx_hi = -1e30f;
        #pragma unroll
        for (int st = 0; st < 8; st++) {
            tmx_lo = fmaxf(tmx_lo, fmaxf(sacc[st][0], sacc[st][1]));
            tmx_hi = fmaxf(tmx_hi, fmaxf(sacc[st][2], sacc[st][3]));
        }
        tmx_lo = fmaxf(tmx_lo, __shfl_xor_sync(0xffffffffu, tmx_lo, 1));
        tmx_lo = fmaxf(tmx_lo, __shfl_xor_sync(0xffffffffu, tmx_lo, 2));
        tmx_hi = fmaxf(tmx_hi, __shfl_xor_sync(0xffffffffu, tmx_hi, 1));
        tmx_hi = fmaxf(tmx_hi, __shfl_xor_sync(0xffffffffu, tmx_hi, 2));

        float mn_lo = fmaxf(m_lo, tmx_lo);
        float mn_hi = fmaxf(m_hi, tmx_hi);
        float al_lo = fast_exp2(m_lo - mn_lo);
        float al_hi = fast_exp2(m_hi - mn_hi);
        m_lo = mn_lo; m_hi = mn_hi;

        float sum_lo = 0.0f, sum_hi = 0.0f;
        #pragma unroll
        for (int st = 0; st < 8; st++) {
            sacc[st][0] = fast_exp2(sacc[st][0] - mn_lo);
            sacc[st][1] = fast_exp2(sacc[st][1] - mn_lo);
            sacc[st][2] = fast_exp2(sacc[st][2] - mn_hi);
            sacc[st][3] = fast_exp2(sacc[st][3] - mn_hi);
            sum_lo += sacc[st][0] + sacc[st][1];
            sum_hi += sacc[st][2] + sacc[st][3];
        }
        sum_lo += __shfl_xor_sync(0xffffffffu, sum_lo, 1);
        sum_lo += __shfl_xor_sync(0xffffffffu, sum_lo, 2);
        sum_hi += __shfl_xor_sync(0xffffffffu, sum_hi, 1);
        sum_hi += __shfl_xor_sync(0xffffffffu, sum_hi, 2);
        l_lo = l_lo * al_lo + sum_lo;
        l_hi = l_hi * al_hi + sum_hi;

        #pragma unroll
        for (int dt = 0; dt < 8; dt++) {
            oacc[dt][0] *= al_lo; oacc[dt][1] *= al_lo;
            oacc[dt][2] *= al_hi; oacc[dt][3] *= al_hi;
        }

        // ---- O += P @ Vc (FULL 4-pass); P frags repacked from registers ----
        #pragma unroll
        for (int kc = 0; kc < 4; kc++) {
            uint32_t aph[4], apl[4];
            {
                float* t0 = sacc[2 * kc];
                float* t1 = sacc[2 * kc + 1];
                #pragma unroll
                for (int q = 0; q < 2; q++) {
                    float a = (q ? t0[2] : t0[0]), b = (q ? t0[3] : t0[1]);
                    __nv_bfloat162 hp = __floats2bfloat162_rn(a, b);
                    float2 hf = __bfloat1622float2(hp);
                    aph[q] = *(uint32_t*)&hp;
                    apl[q] = pack2(a - hf.x, b - hf.y);
                    float c = (q ? t1[2] : t1[0]), d = (q ? t1[3] : t1[1]);
                    __nv_bfloat162 hp2 = __floats2bfloat162_rn(c, d);
                    float2 hf2 = __bfloat1622float2(hp2);
                    aph[q + 2] = *(uint32_t*)&hp2;
                    apl[q + 2] = pack2(c - hf2.x, d - hf2.y);
                }
            }
            #pragma unroll
            for (int dn = 0; dn < 4; dn++) {
                uint32_t off = swz((uint32_t)((kc * 16 + (lane & 15)) * 128 + (dn * 2 + (lane >> 4)) * 16));
                uint32_t bh[4], bl[4];
                ldsm_x4_t(buf + 16384 + off, bh);   // Vh, transposed
                ldsm_x4_t(buf + 24576 + off, bl);   // Vl
                mma16816(oacc[dn * 2],     aph, bh[0], bh[1]);
                mma16816(oacc[dn * 2 + 1], aph, bh[2], bh[3]);
                mma16816(oacc[dn * 2],     aph, bl[0], bl[1]);
                mma16816(oacc[dn * 2 + 1], aph, bl[2], bl[3]);
                mma16816(oacc[dn * 2],     apl, bh[0], bh[1]);
                mma16816(oacc[dn * 2 + 1], apl, bh[2], bh[3]);
                mma16816(oacc[dn * 2],     apl, bl[0], bl[1]);
                mma16816(oacc[dn * 2 + 1], apl, bl[2], bl[3]);
            }
        }
        __syncthreads();
    }

    // ---- epilogue: pooled = oacc/l + C_e (centered), GeM inverse power ----
    int h = nh & 7, n = nh >> 3;
    float il_lo = 1.0f / l_lo, il_hi = 1.0f / l_hi;
    int r_lo = rowBase + wid * 16 + (lane >> 2);
    int r_hi = r_lo + 8;
    #pragma unroll
    for (int dt = 0; dt < 8; dt++) {
        int d = dt * 8 + (lane & 3) * 2;
        int e = h * HD + d;
        float p0 = pp[e], p1 = pp[e + 1];
        float s0 = shift[e], s1 = shift[e + 1];
        float C0 = powf(s0, p0), C1 = powf(s1, p1);   // same centering constant as proj
        float ip0 = 1.0f / p0, ip1 = 1.0f / p1;
        #pragma unroll
        for (int half = 0; half < 2; half++) {
            float il = half ? il_hi : il_lo;
            int r = half ? r_hi : r_lo;
            float pool0 = oacc[dt][half * 2 + 0] * il + C0;
            float pool1 = oacc[dt][half * 2 + 1] * il + C1;
            float v0 = powf(fmaxf(pool0, EPS), ip0) - s0;
            float v1 = powf(fmaxf(pool1, EPS), ip1) - s1;
            __nv_bfloat162 hp = __floats2bfloat162_rn(v0, v1);
            float2 hf = __bfloat1622float2(hp);
            size_t idx = (size_t)(r * NB + n) * EM + e;
            *(uint32_t*)(g_Oh + idx) = *(uint32_t*)&hp;
            *(uint32_t*)(g_Ol + idx) = pack2(v0 - hf.x, v1 - hf.y);
        }
    }
}

// ---------------------------------------------------------------------------
extern "C" void kernel_launch(void* const* d_in, const int* in_sizes, int n_in,
                              void* d_out, int out_size)
{
    const float* query = (const float*)d_in[0];
    const float* keyi  = (const float*)d_in[1];
    const float* value = (const float*)d_in[2];
    const float* ipw   = (const float*)d_in[3];
    const float* ipb   = (const float*)d_in[4];
    const float* opw   = (const float*)d_in[5];
    const float* opb   = (const float*)d_in[6];
    const float* p     = (const float*)d_in[7];
    const float* shift = (const float*)d_in[8];
    float* out = (float*)d_out;

    // 0. split-bf16 conversions
    conv_x_kernel<<<dim3((RR * EM) / 1024, 3), 256>>>(query, keyi, value);
    conv_w_kernel<<<(4 * EM * EM) / 1024, 256>>>(ipw, opw);

    // 1. QKV projection (HMMA split-bf16) -> split-bf16 Q/K/Vc in (n,h,l,d)
    proj_mma_kernel<<<dim3(RR / 128, EM / 128, 3), 256>>>(ipb, p, shift);

    // 2. Flash attention (HMMA split-bf16 4-pass, FMA exp2) -> g_Oh / g_Ol
    int smem = 96 * 1024;
    cudaFuncSetAttribute(attn_mma_kernel, cudaFuncAttributeMaxDynamicSharedMemorySize, smem);
    attn_mma_kernel<<<dim3(L_SEQ / 128, NB * NH), 256, smem>>>(p, shift);

    // 3. Output projection (HMMA split-bf16) -> d_out
    outp_mma_kernel<<<dim3(RR / 128, EM / 128), 256>>>(opb, out);
}